// round 15
// baseline (speedup 1.0000x reference)
#include <cuda_runtime.h>

// DepthDeformConv: B=4, C=64, H=W=128, O=64, 3x3 deformable conv, stride 1, pad 1.
// Fused: per block, 64 contiguous output pixels x all 64 output channels.
// Per kernel tap: bilinear tap precompute -> gather-sample [64c x 64pix] smem tile
// (mask folded into tap weights) -> 64x64x64 GEMM chunk with 4x4 register tiling
// using packed fma.rn.f32x2 (2 fp32 MACs per fma-pipe issue on sm_103a).

#define Bn 4
#define Cc 64
#define Hh 128
#define Ww 128
#define Oo 64
#define Kk 9
#define HW (Hh * Ww)
#define TP 64      // pixels per block tile
#define NT 256     // threads per block

// Pre-transposed weight: [k][c][o] for coalesced per-k slice loads.
__device__ float g_wt[Kk * Cc * Oo];

__global__ void transpose_w_kernel(const float* __restrict__ w) {
    int idx = blockIdx.x * 256 + threadIdx.x;
    if (idx < Oo * Cc * Kk) {
        int o = idx / (Cc * Kk);
        int r = idx % (Cc * Kk);
        int c = r / Kk;
        int k = r % Kk;
        g_wt[(k * Cc + c) * Oo + o] = w[idx];
    }
}

// Packed f32x2 helpers (sm_100+ PTX; ptxas never auto-generates these)
__device__ __forceinline__ unsigned long long splat_f32x2(float v) {
    unsigned long long r;
    asm("mov.b64 %0, {%1, %1};" : "=l"(r) : "f"(v));
    return r;
}
__device__ __forceinline__ void fma_f32x2(unsigned long long& acc,
                                          unsigned long long a,
                                          unsigned long long b) {
    asm("fma.rn.f32x2 %0, %1, %2, %0;" : "+l"(acc) : "l"(a), "l"(b));
}
__device__ __forceinline__ void unpack_f32x2(float& lo, float& hi,
                                             unsigned long long v) {
    asm("mov.b64 {%0, %1}, %2;" : "=f"(lo), "=f"(hi) : "l"(v));
}

__global__ __launch_bounds__(NT) void ddc_kernel(
    const float* __restrict__ input,
    const float* __restrict__ offset,
    const float* __restrict__ mask,
    const float* __restrict__ bias,
    float* __restrict__ out)
{
    __shared__ float s_w[Cc][Oo];     // weight slice for current k: [c][o]
    __shared__ float s_v[Cc][TP];     // sampled tile: [c][pix]
    __shared__ int   s_idx[4][TP];    // bilinear tap indices per pixel
    __shared__ float s_twt[4][TP];    // bilinear tap weights (x validity x mask)

    const int t = threadIdx.x;
    const int bid = blockIdx.x;
    const int pix0 = bid * TP;
    const int b = pix0 / HW;
    const int rem = pix0 % HW;
    const int oh = rem / Ww;
    const int ow0 = rem % Ww;        // multiple of 64 (TP=64, W=128)

    const int tx = t & 15;           // pixel quad: pixels [tx*4, tx*4+4)
    const int ty = t >> 4;           // output quad: outputs [ty*4, ty*4+4)

    // acc2[p][q]: pixel p (of 4), packed output pair q: outputs (4ty+2q, 4ty+2q+1)
    unsigned long long acc2[4][2];
    #pragma unroll
    for (int p = 0; p < 4; p++) {
        acc2[p][0] = 0ull;
        acc2[p][1] = 0ull;
    }

    const float* in_b = input + (size_t)b * Cc * HW;

    // Sampling thread's fixed pixel and starting channel
    const int sp = t & 63;           // pixel handled in sampling phase
    const int sc0 = t >> 6;          // starting channel (advances by 4)

    for (int k = 0; k < Kk; k++) {
        // --- per-pixel bilinear tap precompute (threads 0..63) ---
        // Tap/weight arrays are only read after the next barrier; previous
        // iteration's reads of them finished before the trailing barrier of
        // that iteration, so writing here is race-free.
        if (t < TP) {
            int ow = ow0 + t;
            int oidx = ((b * 18 + 2 * k) * Hh + oh) * Ww + ow;
            float offy = __ldg(&offset[oidx]);
            float offx = __ldg(&offset[oidx + HW]);
            float m = __ldg(&mask[((b * Kk + k) * Hh + oh) * Ww + ow]);
            float py = (float)(oh - 1 + k / 3) + offy;
            float px = (float)(ow - 1 + k % 3) + offx;
            float fy = floorf(py), fx = floorf(px);
            int y0 = (int)fy, x0 = (int)fx;
            float wy = py - fy, wx = px - fx;
            #pragma unroll
            for (int dy = 0; dy < 2; dy++) {
                #pragma unroll
                for (int dx = 0; dx < 2; dx++) {
                    int yi = y0 + dy, xi = x0 + dx;
                    bool valid = (yi >= 0) && (yi < Hh) && (xi >= 0) && (xi < Ww);
                    int yc = min(max(yi, 0), Hh - 1);
                    int xc = min(max(xi, 0), Ww - 1);
                    float wt = (dy ? wy : 1.0f - wy) * (dx ? wx : 1.0f - wx);
                    s_idx[dy * 2 + dx][t] = yc * Ww + xc;
                    s_twt[dy * 2 + dx][t] = valid ? wt * m : 0.0f;
                }
            }
        }

        // --- load weight slice [64c x 64o] for this k (coalesced float4) ---
        {
            const float4* src = (const float4*)(g_wt + k * Cc * Oo);
            float4* dst = (float4*)&s_w[0][0];
            #pragma unroll
            for (int i = 0; i < 4; i++)
                dst[t + i * NT] = src[t + i * NT];
        }
        __syncthreads();   // publish taps + weight slice

        // --- sampling: each thread samples 16 channels of its fixed pixel ---
        {
            int i0 = s_idx[0][sp], i1 = s_idx[1][sp];
            int i2 = s_idx[2][sp], i3 = s_idx[3][sp];
            float w0 = s_twt[0][sp], w1 = s_twt[1][sp];
            float w2 = s_twt[2][sp], w3 = s_twt[3][sp];
            #pragma unroll
            for (int i = 0; i < 16; i++) {
                int c = sc0 + i * 4;
                const float* in_c = in_b + c * HW;
                float v = w0 * __ldg(&in_c[i0]) + w1 * __ldg(&in_c[i1])
                        + w2 * __ldg(&in_c[i2]) + w3 * __ldg(&in_c[i3]);
                s_v[c][sp] = v;
            }
        }
        __syncthreads();   // publish s_v

        // --- GEMM chunk: acc[o][p] += sum_c s_v[c][p] * s_w[c][o] ---
        // Packed along outputs: one LDS.128 of w gives two natural f32x2 pairs;
        // v is splat per pixel (alu pipe, overlapped with fma pipe).
        #pragma unroll
        for (int c = 0; c < Cc; c++) {
            ulonglong2 ww = *(const ulonglong2*)&s_w[c][ty * 4]; // (w0,w1),(w2,w3)
            float4 v4 = *(const float4*)&s_v[c][tx * 4];
            unsigned long long vs0 = splat_f32x2(v4.x);
            unsigned long long vs1 = splat_f32x2(v4.y);
            unsigned long long vs2 = splat_f32x2(v4.z);
            unsigned long long vs3 = splat_f32x2(v4.w);
            fma_f32x2(acc2[0][0], vs0, ww.x);
            fma_f32x2(acc2[0][1], vs0, ww.y);
            fma_f32x2(acc2[1][0], vs1, ww.x);
            fma_f32x2(acc2[1][1], vs1, ww.y);
            fma_f32x2(acc2[2][0], vs2, ww.x);
            fma_f32x2(acc2[2][1], vs2, ww.y);
            fma_f32x2(acc2[3][0], vs3, ww.x);
            fma_f32x2(acc2[3][1], vs3, ww.y);
        }
        __syncthreads();   // GEMM reads done before next iteration overwrites tiles
    }

    // --- epilogue: unpack pairs, add bias, write coalesced float4 ---
    float fo[4][4];   // fo[i][p]: output 4ty+i, pixel tx*4+p
    #pragma unroll
    for (int p = 0; p < 4; p++) {
        #pragma unroll
        for (int q = 0; q < 2; q++) {
            float lo, hi;
            unpack_f32x2(lo, hi, acc2[p][q]);
            fo[2 * q][p] = lo;
            fo[2 * q + 1][p] = hi;
        }
    }
    const float4 bz4 = *(const float4*)&bias[ty * 4];
    const float bb[4] = {bz4.x, bz4.y, bz4.z, bz4.w};
    #pragma unroll
    for (int i = 0; i < 4; i++) {
        int o = ty * 4 + i;
        float4 r;
        r.x = fo[i][0] + bb[i];
        r.y = fo[i][1] + bb[i];
        r.z = fo[i][2] + bb[i];
        r.w = fo[i][3] + bb[i];
        *(float4*)&out[((size_t)(b * Oo + o) * Hh + oh) * Ww + ow0 + tx * 4] = r;
    }
}

extern "C" void kernel_launch(void* const* d_in, const int* in_sizes, int n_in,
                              void* d_out, int out_size) {
    const float* input  = (const float*)d_in[0];
    // d_in[1] = depth (unused by reference)
    const float* offset = (const float*)d_in[2];
    const float* mask   = (const float*)d_in[3];
    const float* weight = (const float*)d_in[4];
    const float* bias   = (const float*)d_in[5];
    float* out = (float*)d_out;

    transpose_w_kernel<<<(Oo * Cc * Kk + 255) / 256, 256>>>(weight);

    int nblocks = (Bn * HW) / TP;   // 1024
    ddc_kernel<<<nblocks, NT>>>(input, offset, mask, bias, out);
}

// round 17
// speedup vs baseline: 1.0033x; 1.0033x over previous
#include <cuda_runtime.h>

// DepthDeformConv: B=4, C=64, H=W=128, O=64, 3x3 deformable conv, stride 1, pad 1.
// Fused per-tap pipeline. Round-16 changes vs 196us baseline:
//  A) bilinear gather via precomputed float2 pairs array: 2x LDG.64 per
//     channel-point instead of 4x LDG.32 (edge cases folded into weights)
//  B) GEMM warp remap (4 pixel-quads x 8 output-quads per warp): 192B distinct
//     smem per warp-c-iter instead of 288B.

#define Bn 4
#define Cc 64
#define Hh 128
#define Ww 128
#define Oo 64
#define Kk 9
#define HW (Hh * Ww)
#define TP 64      // pixels per block tile
#define NT 256     // threads per block
#define NTOT (Bn * Cc * HW)

// Pre-transposed weight: [k][c][o] for coalesced per-k slice loads.
__device__ float g_wt[Kk * Cc * Oo];
// Pairs array: g_pairs[i] = (input[i], input[i+1]) — 8B-aligned bilinear pair loads.
__device__ float2 g_pairs[NTOT];

__global__ void transpose_w_kernel(const float* __restrict__ w) {
    int idx = blockIdx.x * 256 + threadIdx.x;
    if (idx < Oo * Cc * Kk) {
        int o = idx / (Cc * Kk);
        int r = idx % (Cc * Kk);
        int c = r / Kk;
        int k = r % Kk;
        g_wt[(k * Cc + c) * Oo + o] = w[idx];
    }
}

__global__ void build_pairs_kernel(const float* __restrict__ in) {
    int i = blockIdx.x * 256 + threadIdx.x;
    if (i < NTOT) {
        float a = in[i];
        float bv = (i + 1 < NTOT) ? in[i + 1] : 0.0f;
        g_pairs[i] = make_float2(a, bv);
    }
}

// Packed f32x2 helpers (sm_100+ PTX; ptxas never auto-generates these)
__device__ __forceinline__ unsigned long long splat_f32x2(float v) {
    unsigned long long r;
    asm("mov.b64 %0, {%1, %1};" : "=l"(r) : "f"(v));
    return r;
}
__device__ __forceinline__ void fma_f32x2(unsigned long long& acc,
                                          unsigned long long a,
                                          unsigned long long b) {
    asm("fma.rn.f32x2 %0, %1, %2, %0;" : "+l"(acc) : "l"(a), "l"(b));
}
__device__ __forceinline__ void unpack_f32x2(float& lo, float& hi,
                                             unsigned long long v) {
    asm("mov.b64 {%0, %1}, %2;" : "=f"(lo), "=f"(hi) : "l"(v));
}

__global__ __launch_bounds__(NT) void ddc_kernel(
    const float* __restrict__ offset,
    const float* __restrict__ mask,
    const float* __restrict__ bias,
    float* __restrict__ out)
{
    __shared__ float  s_w[Cc][Oo];     // weight slice for current k: [c][o]
    __shared__ float  s_v[Cc][TP];     // sampled tile: [c][pix]
    __shared__ int    s_idx[2][TP];    // per-pixel pair addresses (row 0/1)
    __shared__ float2 s_wAB[2][TP];    // per-pixel pair weights (validity+mask+edge folded)

    const int t = threadIdx.x;
    const int bid = blockIdx.x;
    const int pix0 = bid * TP;
    const int b = pix0 / HW;
    const int rem = pix0 % HW;
    const int oh = rem / Ww;
    const int ow0 = rem % Ww;        // multiple of 64 (TP=64, W=128)

    // GEMM warp remap: warp spans 4 pixel-quads x 8 output-quads.
    const int l = t & 31;
    const int wrp = t >> 5;
    const int tx = (wrp & 3) * 4 + (l & 3);      // pixel quad 0..15
    const int ty = (wrp >> 2) * 8 + (l >> 2);    // output quad 0..15

    // acc2[p][q]: pixel p (of 4), packed output pair q: outputs (4ty+2q, 4ty+2q+1)
    unsigned long long acc2[4][2];
    #pragma unroll
    for (int p = 0; p < 4; p++) {
        acc2[p][0] = 0ull;
        acc2[p][1] = 0ull;
    }

    const float2* pairs_b = g_pairs + (size_t)b * Cc * HW;

    // Sampling thread's fixed pixel and starting channel
    const int sp = t & 63;           // pixel handled in sampling phase
    const int sc0 = t >> 6;          // starting channel (advances by 4)

    for (int k = 0; k < Kk; k++) {
        // --- per-pixel bilinear pair precompute (threads 0..63) ---
        if (t < TP) {
            int ow = ow0 + t;
            int oidx = ((b * 18 + 2 * k) * Hh + oh) * Ww + ow;
            float offy = __ldg(&offset[oidx]);
            float offx = __ldg(&offset[oidx + HW]);
            float m = __ldg(&mask[((b * Kk + k) * Hh + oh) * Ww + ow]);
            float py = (float)(oh - 1 + k / 3) + offy;
            float px = (float)(ow - 1 + k % 3) + offx;
            float fy = floorf(py), fx = floorf(px);
            int y0 = (int)fy, x0 = (int)fx;
            float wy = py - fy, wx = px - fx;

            // x handling shared by both rows
            int xc = min(max(x0, 0), Ww - 2);
            bool vl = (x0 >= 0) && (x0 < Ww);        // left tap valid
            bool vr = (x0 + 1 >= 0) && (x0 + 1 < Ww); // right tap valid

            #pragma unroll
            for (int r = 0; r < 2; r++) {
                int yr = y0 + r;
                bool rowv = (yr >= 0) && (yr < Hh);
                int yc = min(max(yr, 0), Hh - 1);
                float wyr = (r ? wy : 1.0f - wy) * m;
                float wl = (rowv && vl) ? wyr * (1.0f - wx) : 0.0f;
                float wr_ = (rowv && vr) ? wyr * wx : 0.0f;
                // Remap (wl,wr) onto the float2 lanes at clamped xc:
                //   normal (x0==xc):         (wA,wB) = (wl, wr)
                //   x0==-1 (xc=0):           pair.x = v[x0+1]  -> wA=wr, wB=0
                //   x0==127 (xc=126):        pair.y = v[x0]    -> wA=0,  wB=wl
                float wA = (x0 == xc) ? wl : ((x0 + 1 == xc) ? wr_ : 0.0f);
                float wB = (x0 + 1 == xc + 1) ? wr_ : ((x0 == xc + 1) ? wl : 0.0f);
                s_idx[r][t] = yc * Ww + xc;
                s_wAB[r][t] = make_float2(wA, wB);
            }
        }

        // --- load weight slice [64c x 64o] for this k (coalesced float4) ---
        {
            const float4* src = (const float4*)(g_wt + k * Cc * Oo);
            float4* dst = (float4*)&s_w[0][0];
            #pragma unroll
            for (int i = 0; i < 4; i++)
                dst[t + i * NT] = src[t + i * NT];
        }
        __syncthreads();   // publish taps + weight slice

        // --- sampling: each thread samples 16 channels of its fixed pixel ---
        {
            int a0 = s_idx[0][sp], a1 = s_idx[1][sp];
            float2 w0 = s_wAB[0][sp], w1 = s_wAB[1][sp];
            #pragma unroll
            for (int i = 0; i < 16; i++) {
                int c = sc0 + i * 4;
                const float2* pc = pairs_b + (size_t)c * HW;
                float2 f0 = __ldg(&pc[a0]);
                float2 f1 = __ldg(&pc[a1]);
                float v = w0.x * f0.x + w0.y * f0.y
                        + w1.x * f1.x + w1.y * f1.y;
                s_v[c][sp] = v;
            }
        }
        __syncthreads();   // publish s_v

        // --- GEMM chunk: acc[o][p] += sum_c s_v[c][p] * s_w[c][o] ---
        #pragma unroll
        for (int c = 0; c < Cc; c++) {
            ulonglong2 ww = *(const ulonglong2*)&s_w[c][ty * 4]; // (w0,w1),(w2,w3)
            float4 v4 = *(const float4*)&s_v[c][tx * 4];
            unsigned long long vs0 = splat_f32x2(v4.x);
            unsigned long long vs1 = splat_f32x2(v4.y);
            unsigned long long vs2 = splat_f32x2(v4.z);
            unsigned long long vs3 = splat_f32x2(v4.w);
            fma_f32x2(acc2[0][0], vs0, ww.x);
            fma_f32x2(acc2[0][1], vs0, ww.y);
            fma_f32x2(acc2[1][0], vs1, ww.x);
            fma_f32x2(acc2[1][1], vs1, ww.y);
            fma_f32x2(acc2[2][0], vs2, ww.x);
            fma_f32x2(acc2[2][1], vs2, ww.y);
            fma_f32x2(acc2[3][0], vs3, ww.x);
            fma_f32x2(acc2[3][1], vs3, ww.y);
        }
        __syncthreads();   // GEMM reads done before next iteration overwrites tiles
    }

    // --- epilogue: unpack pairs, add bias, write coalesced float4 ---
    float fo[4][4];   // fo[i][p]: output 4ty+i, pixel tx*4+p
    #pragma unroll
    for (int p = 0; p < 4; p++) {
        #pragma unroll
        for (int q = 0; q < 2; q++) {
            float lo, hi;
            unpack_f32x2(lo, hi, acc2[p][q]);
            fo[2 * q][p] = lo;
            fo[2 * q + 1][p] = hi;
        }
    }
    const float4 bz4 = *(const float4*)&bias[ty * 4];
    const float bb[4] = {bz4.x, bz4.y, bz4.z, bz4.w};
    #pragma unroll
    for (int i = 0; i < 4; i++) {
        int o = ty * 4 + i;
        float4 r;
        r.x = fo[i][0] + bb[i];
        r.y = fo[i][1] + bb[i];
        r.z = fo[i][2] + bb[i];
        r.w = fo[i][3] + bb[i];
        *(float4*)&out[((size_t)(b * Oo + o) * Hh + oh) * Ww + ow0 + tx * 4] = r;
    }
}

extern "C" void kernel_launch(void* const* d_in, const int* in_sizes, int n_in,
                              void* d_out, int out_size) {
    const float* input  = (const float*)d_in[0];
    // d_in[1] = depth (unused by reference)
    const float* offset = (const float*)d_in[2];
    const float* mask   = (const float*)d_in[3];
    const float* weight = (const float*)d_in[4];
    const float* bias   = (const float*)d_in[5];
    float* out = (float*)d_out;

    transpose_w_kernel<<<(Oo * Cc * Kk + 255) / 256, 256>>>(weight);
    build_pairs_kernel<<<(NTOT + 255) / 256, 256>>>(input);

    int nblocks = (Bn * HW) / TP;   // 1024
    ddc_kernel<<<nblocks, NT>>>(offset, mask, bias, out);
}